// round 12
// baseline (speedup 1.0000x reference)
#include <cuda_runtime.h>
#include <cuda_fp16.h>
#include <cstdint>

#define ALPHA 0.2f
#define BN_EPS 1e-5f
#define MAXN 50176

// ---------------- scratch (device globals) ----------------
__device__ float g_z[(size_t)MAXN * 128];
__device__ float g_bufA[(size_t)MAXN * 128];
__device__ float g_bufB[(size_t)MAXN * 128];
__device__ __half g_Bth[3][128 * 128];        // pre-transposed [n][k] fp16 weights
__device__ float g_wa[128];
__device__ float g_ws[128];
__device__ float g_sum[3 * 128];
__device__ float g_sqs[3 * 128];

__device__ __forceinline__ float lrelu(float x) { return x > 0.f ? x : ALPHA * x; }

// ---------------- unified prep: block 0 = wa/ws/zero, blocks 1-64 = WcT, 65-192 = W2/W3 ----------
__global__ __launch_bounds__(256) void prep_all_kernel(
    const float* __restrict__ Wt, const float* __restrict__ a_att,
    const float* __restrict__ W1, const float* __restrict__ W2, const float* __restrict__ W3)
{
    int b = blockIdx.x;
    int tid = threadIdx.x;

    if (b == 0) {
        if (tid < 128) {
            int d = tid;
            float wa = 0.f, ws = 0.f;
            #pragma unroll 8
            for (int t = 0; t < 128; ++t) {
                float w = Wt[d * 128 + t];
                ws += w * a_att[t];
                wa += w * a_att[128 + t];
            }
            g_wa[d] = wa;
            g_ws[d] = ws;
            #pragma unroll
            for (int l = 0; l < 3; ++l) { g_sum[l * 128 + d] = 0.f; g_sqs[l * 128 + d] = 0.f; }
        }
    } else if (b <= 64) {
        // Bth[0][n][k] = half((Wt@W1)[k][n]); two n per block
        __shared__ float s_w1[2][128];
        int half_id = tid >> 7;           // 0..1
        int k = tid & 127;
        int n = (b - 1) * 2 + half_id;
        s_w1[half_id][k] = W1[k * 128 + n];
        __syncthreads();
        float acc = 0.f;
        #pragma unroll 4
        for (int t = 0; t < 128; ++t) acc += Wt[k * 128 + t] * s_w1[half_id][t];
        g_Bth[0][n * 128 + k] = __float2half_rn(acc);
    } else {
        // Bth[1],Bth[2]: W2,W3 [k][n] -> [n][k]
        int idx = (b - 65) * 256 + tid;   // 0..32767
        int layer = idx >> 14;
        int r = idx & 16383;
        int k = r >> 7, n = r & 127;
        const float* src = layer ? W3 : W2;
        g_Bth[1 + layer][n * 128 + k] = __float2half_rn(src[k * 128 + n]);
    }
}

// ---------------- fused attention: block per node (FROZEN: 124us @ 70% DRAM) ----------------
__global__ __launch_bounds__(128) void attn_kernel(
    const float* __restrict__ self, const float* __restrict__ neigh,
    const float* __restrict__ epsp, int N, int K)
{
    __shared__ float s_raw[32];
    __shared__ float s_attn[32];
    __shared__ float s_sred[4];
    __shared__ float4 s_part[4][32];

    int n = blockIdx.x;
    int tid = threadIdx.x, warp = tid >> 5, lane = tid & 31;

    const float4* nb = (const float4*)neigh + (size_t)n * K * 32;
    const float4* sv = (const float4*)self + (size_t)n * 32;

    float4 wa4 = ((const float4*)g_wa)[lane];

    float sp = self[(size_t)n * 128 + tid] * g_ws[tid];
    #pragma unroll
    for (int off = 16; off; off >>= 1) sp += __shfl_xor_sync(0xffffffffu, sp, off);
    if (lane == 0) s_sred[warp] = sp;

    float4 v[7];
    #pragma unroll
    for (int j = 0; j < 7; ++j) {
        int k = warp + 4 * j;
        v[j] = (k < K) ? nb[k * 32 + lane] : make_float4(0.f, 0.f, 0.f, 0.f);
    }

    #pragma unroll
    for (int j = 0; j < 7; ++j) {
        int k = warp + 4 * j;
        if (k < K) {
            float s = v[j].x * wa4.x + v[j].y * wa4.y + v[j].z * wa4.z + v[j].w * wa4.w;
            #pragma unroll
            for (int off = 16; off; off >>= 1) s += __shfl_xor_sync(0xffffffffu, s, off);
            if (lane == 0) s_raw[k] = s;
        }
    }
    __syncthreads();

    if (warp == 0) {
        float ssum = s_sred[0] + s_sred[1] + s_sred[2] + s_sred[3];
        float val = -1e30f;
        if (lane < K) val = lrelu(ssum + s_raw[lane]);
        float m = val;
        #pragma unroll
        for (int off = 16; off; off >>= 1) m = fmaxf(m, __shfl_xor_sync(0xffffffffu, m, off));
        float e = (lane < K) ? expf(val - m) : 0.f;
        float s = e;
        #pragma unroll
        for (int off = 16; off; off >>= 1) s += __shfl_xor_sync(0xffffffffu, s, off);
        s_attn[lane] = e / s;
    }
    __syncthreads();

    float4 acc = make_float4(0.f, 0.f, 0.f, 0.f);
    #pragma unroll
    for (int j = 0; j < 7; ++j) {
        int k = warp + 4 * j;
        if (k < K) {
            float a = s_attn[k];
            acc.x += a * v[j].x; acc.y += a * v[j].y;
            acc.z += a * v[j].z; acc.w += a * v[j].w;
        }
    }
    s_part[warp][lane] = acc;
    __syncthreads();

    if (warp == 0) {
        float4 r0 = s_part[0][lane], r1 = s_part[1][lane];
        float4 r2 = s_part[2][lane], r3 = s_part[3][lane];
        float ce = 1.f + epsp[0];
        float4 sf = sv[lane];
        float4 r;
        r.x = r0.x + r1.x + r2.x + r3.x + ce * sf.x;
        r.y = r0.y + r1.y + r2.y + r3.y + ce * sf.y;
        r.z = r0.z + r1.z + r2.z + r3.z + ce * sf.z;
        r.w = r0.w + r1.w + r2.w + r3.w + ce * sf.w;
        ((float4*)g_z)[(size_t)n * 32 + lane] = r;
    }
}

// ---------------- fp16 m16n8k16 mma.sync GEMM, BM=32, 5 CTAs/SM, inline BN-fin + fused stats ----
// smem: [0:1024) scale|shift (floats), then As half[32][136], Bs half[128][136]
#define ASTRIDE 136
#define SMEM_BYTES (1024 + 32 * ASTRIDE * 2 + 128 * ASTRIDE * 2)   // 44544

template <bool IN_BN>
__global__ __launch_bounds__(256, 5) void gemm_mma(
    const float* __restrict__ A, const __half* __restrict__ Bth,
    const float* __restrict__ sumIn, const float* __restrict__ sqsIn,
    const float* __restrict__ gIn, const float* __restrict__ beIn,
    float* __restrict__ Y, float* __restrict__ sumOut, float* __restrict__ sqsOut,
    float invN, int N)
{
    extern __shared__ char smc[];
    float* s_scale = (float*)smc;                     // 128
    float* s_shift = (float*)smc + 128;               // 128
    __half* As = (__half*)(smc + 1024);               // 32*136
    __half* Bs = As + 32 * ASTRIDE;                   // 128*136

    const int tid = threadIdx.x;
    const int wid = tid >> 5, lane = tid & 31;
    const int g = lane >> 2, t = lane & 3;
    const int warprow = wid & 1;     // 0..1 (16-row halves)
    const int warpcol = wid >> 1;    // 0..3 (32-col quarters)
    const int rowBase = blockIdx.x * 32;

    // inline BN finalize
    if (IN_BN && tid < 128) {
        float m = sumIn[tid] * invN;
        float var = sqsIn[tid] * invN - m * m;
        float s = gIn[tid] * rsqrtf(var + BN_EPS);
        s_scale[tid] = s;
        s_shift[tid] = beIn[tid] - m * s;
    }

    // B: copy fp16 weights (4096 uint2), padded stride
    {
        const uint2* Bi = (const uint2*)Bth;
        #pragma unroll
        for (int i = 0; i < 16; ++i) {
            int idx = tid + i * 256;
            int n = idx >> 5, q = idx & 31;
            *(uint2*)(Bs + n * ASTRIDE + q * 4) = Bi[idx];
        }
    }
    if (IN_BN) __syncthreads();

    // A: 32 rows x 128, BN+lrelu fused, fp16-converted; rows >= N exact zero
    {
        const float4* Ag4 = (const float4*)A;
        #pragma unroll
        for (int i = 0; i < 4; ++i) {
            int idx = tid + i * 256;
            int row = idx >> 5, q = idx & 31;
            int grow = rowBase + row;
            float4 a = make_float4(0.f, 0.f, 0.f, 0.f);
            if (grow < N) {
                a = Ag4[(size_t)grow * 32 + q];
                if (IN_BN) {
                    float4 sc = *(const float4*)&s_scale[q * 4];
                    float4 sh = *(const float4*)&s_shift[q * 4];
                    a.x = lrelu(sc.x * a.x + sh.x);
                    a.y = lrelu(sc.y * a.y + sh.y);
                    a.z = lrelu(sc.z * a.z + sh.z);
                    a.w = lrelu(sc.w * a.w + sh.w);
                }
            }
            __half2 h01 = __floats2half2_rn(a.x, a.y);
            __half2 h23 = __floats2half2_rn(a.z, a.w);
            uint2 pk;
            pk.x = *(uint32_t*)&h01;
            pk.y = *(uint32_t*)&h23;
            *(uint2*)(As + row * ASTRIDE + q * 4) = pk;
        }
    }
    __syncthreads();

    float acc[4][4];
    #pragma unroll
    for (int n = 0; n < 4; ++n)
        #pragma unroll
        for (int j = 0; j < 4; ++j) acc[n][j] = 0.f;

    #pragma unroll
    for (int ks = 0; ks < 8; ++ks) {
        const int k0 = ks * 16;
        uint32_t af[4];
        {
            const __half* p = As + (warprow * 16 + g) * ASTRIDE + k0 + 2 * t;
            af[0] = *(const uint32_t*)p;
            af[1] = *(const uint32_t*)(p + 8 * ASTRIDE);
            af[2] = *(const uint32_t*)(p + 8);
            af[3] = *(const uint32_t*)(p + 8 * ASTRIDE + 8);
        }
        #pragma unroll
        for (int n = 0; n < 4; ++n) {
            const __half* pb = Bs + (warpcol * 32 + n * 8 + g) * ASTRIDE + k0 + 2 * t;
            uint32_t b0 = *(const uint32_t*)pb;
            uint32_t b1 = *(const uint32_t*)(pb + 8);
            asm volatile(
                "mma.sync.aligned.m16n8k16.row.col.f32.f16.f16.f32 "
                "{%0,%1,%2,%3}, {%4,%5,%6,%7}, {%8,%9}, {%0,%1,%2,%3};"
                : "+f"(acc[n][0]), "+f"(acc[n][1]),
                  "+f"(acc[n][2]), "+f"(acc[n][3])
                : "r"(af[0]), "r"(af[1]), "r"(af[2]), "r"(af[3]),
                  "r"(b0), "r"(b1));
        }
    }
    __syncthreads();   // smem free for stats reduce

    // epilogue: store + per-column stats (rows >= N contribute exact zeros)
    float cs[8], cq[8];
    #pragma unroll
    for (int j = 0; j < 8; ++j) { cs[j] = 0.f; cq[j] = 0.f; }

    {
        int r = rowBase + warprow * 16 + g;
        #pragma unroll
        for (int n = 0; n < 4; ++n) {
            int c = warpcol * 32 + n * 8 + 2 * t;
            float y0 = acc[n][0], y1 = acc[n][1];
            float y2 = acc[n][2], y3 = acc[n][3];
            *(float2*)&Y[(size_t)r * 128 + c]       = make_float2(y0, y1);
            *(float2*)&Y[(size_t)(r + 8) * 128 + c] = make_float2(y2, y3);
            int j = n * 2;
            cs[j]     += y0 + y2;  cq[j]     += y0 * y0 + y2 * y2;
            cs[j + 1] += y1 + y3;  cq[j + 1] += y1 * y1 + y3 * y3;
        }
    }

    #pragma unroll
    for (int off = 4; off < 32; off <<= 1) {
        #pragma unroll
        for (int j = 0; j < 8; ++j) {
            cs[j] += __shfl_xor_sync(0xffffffffu, cs[j], off);
            cq[j] += __shfl_xor_sync(0xffffffffu, cq[j], off);
        }
    }

    float* red_s = (float*)smc;            // 8 warps x 32 cols
    float* red_q = (float*)smc + 256;
    if (lane < 4) {
        #pragma unroll
        for (int j = 0; j < 8; ++j) {
            int n = j >> 1;
            int cl = n * 8 + 2 * lane + (j & 1);
            red_s[wid * 32 + cl] = cs[j];
            red_q[wid * 32 + cl] = cq[j];
        }
    }
    __syncthreads();
    if (tid < 128) {
        int wc = tid >> 5, cl = tid & 31;
        float ssum = red_s[(2 * wc) * 32 + cl] + red_s[(2 * wc + 1) * 32 + cl];
        float qsum = red_q[(2 * wc) * 32 + cl] + red_q[(2 * wc + 1) * 32 + cl];
        atomicAdd(&sumOut[wc * 32 + cl], ssum);
        atomicAdd(&sqsOut[wc * 32 + cl], qsum);
    }
}

// ---------------- final BN + leaky_relu apply (inline BN finalize) ----------------
__global__ __launch_bounds__(256) void apply_kernel(
    const float* __restrict__ Y,
    const float* __restrict__ sumIn, const float* __restrict__ sqsIn,
    const float* __restrict__ gIn, const float* __restrict__ beIn,
    float* __restrict__ out, float invN, int N)
{
    __shared__ float s_scale[128], s_shift[128];
    int tid = threadIdx.x;
    if (tid < 128) {
        float m = sumIn[tid] * invN;
        float var = sqsIn[tid] * invN - m * m;
        float s = gIn[tid] * rsqrtf(var + BN_EPS);
        s_scale[tid] = s;
        s_shift[tid] = beIn[tid] - m * s;
    }
    __syncthreads();

    size_t i = (size_t)blockIdx.x * blockDim.x + tid;
    if (i < (size_t)N * 32) {
        int c = (int)(i & 31);
        float4 sc = *(const float4*)&s_scale[c * 4];
        float4 sh = *(const float4*)&s_shift[c * 4];
        float4 y = ((const float4*)Y)[i];
        float4 o;
        o.x = lrelu(sc.x * y.x + sh.x);
        o.y = lrelu(sc.y * y.y + sh.y);
        o.z = lrelu(sc.z * y.z + sh.z);
        o.w = lrelu(sc.w * y.w + sh.w);
        ((float4*)out)[i] = o;
    }
}

// ---------------- launch ----------------
extern "C" void kernel_launch(void* const* d_in, const int* in_sizes, int n_in,
                              void* d_out, int out_size) {
    const float* self  = (const float*)d_in[0];
    const float* neigh = (const float*)d_in[1];
    const float* W_t   = (const float*)d_in[2];
    const float* a_att = (const float*)d_in[3];
    const float* epsp  = (const float*)d_in[4];
    const float* W1 = (const float*)d_in[5];
    const float* g1 = (const float*)d_in[7];
    const float* be1 = (const float*)d_in[8];
    const float* W2 = (const float*)d_in[9];
    const float* g2 = (const float*)d_in[11];
    const float* be2 = (const float*)d_in[12];
    const float* W3 = (const float*)d_in[13];
    const float* g3 = (const float*)d_in[15];
    const float* be3 = (const float*)d_in[16];

    int N = in_sizes[0] / 128;
    int K = (int)((long long)in_sizes[1] / ((long long)N * 128));

    float *z, *bufA, *bufB, *sum, *sqs;
    __half* Bth;
    cudaGetSymbolAddress((void**)&z,    g_z);
    cudaGetSymbolAddress((void**)&bufA, g_bufA);
    cudaGetSymbolAddress((void**)&bufB, g_bufB);
    cudaGetSymbolAddress((void**)&Bth,  g_Bth);
    cudaGetSymbolAddress((void**)&sum,  g_sum);
    cudaGetSymbolAddress((void**)&sqs,  g_sqs);

    cudaFuncSetAttribute(gemm_mma<false>, cudaFuncAttributeMaxDynamicSharedMemorySize, SMEM_BYTES);
    cudaFuncSetAttribute(gemm_mma<true>,  cudaFuncAttributeMaxDynamicSharedMemorySize, SMEM_BYTES);

    float invN = 1.f / (float)N;
    int gemmGrid = (N + 31) / 32;

    prep_all_kernel<<<193, 256>>>(W_t, a_att, W1, W2, W3);

    attn_kernel<<<N, 128>>>(self, neigh, epsp, N, K);

    // y1 = z @ Wc (bias no-op under BN), fused stats -> sum[0]
    gemm_mma<false><<<gemmGrid, 256, SMEM_BYTES>>>(
        z, Bth, nullptr, nullptr, nullptr, nullptr, bufA, sum, sqs, invN, N);

    // y2 = act1(y1) @ W2, inline bn_fin(layer0), fused stats -> sum[1]
    gemm_mma<true><<<gemmGrid, 256, SMEM_BYTES>>>(
        bufA, Bth + 16384, sum, sqs, g1, be1, bufB, sum + 128, sqs + 128, invN, N);

    // y3 = act2(y2) @ W3, inline bn_fin(layer1), fused stats -> sum[2]
    gemm_mma<true><<<gemmGrid, 256, SMEM_BYTES>>>(
        bufB, Bth + 32768, sum + 128, sqs + 128, g2, be2, bufA, sum + 256, sqs + 256, invN, N);

    // out = act3(y3), inline bn_fin(layer2)
    int applyGrid = (int)(((size_t)N * 32 + 255) / 256);
    apply_kernel<<<applyGrid, 256>>>(bufA, sum + 256, sqs + 256, g3, be3, (float*)d_out, invN, N);
}

// round 13
// speedup vs baseline: 1.0822x; 1.0822x over previous
#include <cuda_runtime.h>
#include <cuda_fp16.h>
#include <cstdint>

#define ALPHA 0.2f
#define BN_EPS 1e-5f
#define MAXN 50176

// ---------------- scratch (device globals) ----------------
__device__ float g_z[(size_t)MAXN * 128];
__device__ float g_bufA[(size_t)MAXN * 128];
__device__ float g_bufB[(size_t)MAXN * 128];
__device__ __half g_Bth[3][128 * 128];        // pre-transposed [n][k] fp16 weights
__device__ float g_wa[128];
__device__ float g_ws[128];
__device__ float g_sum[3 * 128];
__device__ float g_sqs[3 * 128];

__device__ __forceinline__ float lrelu(float x) { return x > 0.f ? x : ALPHA * x; }

// ---------------- unified prep: block 0 = wa/ws/zero, blocks 1-64 = WcT, 65-192 = W2/W3 ----------
__global__ __launch_bounds__(256) void prep_all_kernel(
    const float* __restrict__ Wt, const float* __restrict__ a_att,
    const float* __restrict__ W1, const float* __restrict__ W2, const float* __restrict__ W3)
{
    int b = blockIdx.x;
    int tid = threadIdx.x;

    if (b == 0) {
        if (tid < 128) {
            int d = tid;
            float wa = 0.f, ws = 0.f;
            #pragma unroll 8
            for (int t = 0; t < 128; ++t) {
                float w = Wt[d * 128 + t];
                ws += w * a_att[t];
                wa += w * a_att[128 + t];
            }
            g_wa[d] = wa;
            g_ws[d] = ws;
            #pragma unroll
            for (int l = 0; l < 3; ++l) { g_sum[l * 128 + d] = 0.f; g_sqs[l * 128 + d] = 0.f; }
        }
    } else if (b <= 64) {
        // Bth[0][n][k] = half((Wt@W1)[k][n]); two n per block
        __shared__ float s_w1[2][128];
        int half_id = tid >> 7;           // 0..1
        int k = tid & 127;
        int n = (b - 1) * 2 + half_id;
        s_w1[half_id][k] = W1[k * 128 + n];
        __syncthreads();
        float acc = 0.f;
        #pragma unroll 4
        for (int t = 0; t < 128; ++t) acc += Wt[k * 128 + t] * s_w1[half_id][t];
        g_Bth[0][n * 128 + k] = __float2half_rn(acc);
    } else {
        // Bth[1],Bth[2]: W2,W3 [k][n] -> [n][k]
        int idx = (b - 65) * 256 + tid;   // 0..32767
        int layer = idx >> 14;
        int r = idx & 16383;
        int k = r >> 7, n = r & 127;
        const float* src = layer ? W3 : W2;
        g_Bth[1 + layer][n * 128 + k] = __float2half_rn(src[k * 128 + n]);
    }
}

// ---------------- fused attention: block per node (FROZEN: 124us @ 70% DRAM) ----------------
__global__ __launch_bounds__(128) void attn_kernel(
    const float* __restrict__ self, const float* __restrict__ neigh,
    const float* __restrict__ epsp, int N, int K)
{
    __shared__ float s_raw[32];
    __shared__ float s_attn[32];
    __shared__ float s_sred[4];
    __shared__ float4 s_part[4][32];

    int n = blockIdx.x;
    int tid = threadIdx.x, warp = tid >> 5, lane = tid & 31;

    const float4* nb = (const float4*)neigh + (size_t)n * K * 32;
    const float4* sv = (const float4*)self + (size_t)n * 32;

    float4 wa4 = ((const float4*)g_wa)[lane];

    float sp = self[(size_t)n * 128 + tid] * g_ws[tid];
    #pragma unroll
    for (int off = 16; off; off >>= 1) sp += __shfl_xor_sync(0xffffffffu, sp, off);
    if (lane == 0) s_sred[warp] = sp;

    float4 v[7];
    #pragma unroll
    for (int j = 0; j < 7; ++j) {
        int k = warp + 4 * j;
        v[j] = (k < K) ? nb[k * 32 + lane] : make_float4(0.f, 0.f, 0.f, 0.f);
    }

    #pragma unroll
    for (int j = 0; j < 7; ++j) {
        int k = warp + 4 * j;
        if (k < K) {
            float s = v[j].x * wa4.x + v[j].y * wa4.y + v[j].z * wa4.z + v[j].w * wa4.w;
            #pragma unroll
            for (int off = 16; off; off >>= 1) s += __shfl_xor_sync(0xffffffffu, s, off);
            if (lane == 0) s_raw[k] = s;
        }
    }
    __syncthreads();

    if (warp == 0) {
        float ssum = s_sred[0] + s_sred[1] + s_sred[2] + s_sred[3];
        float val = -1e30f;
        if (lane < K) val = lrelu(ssum + s_raw[lane]);
        float m = val;
        #pragma unroll
        for (int off = 16; off; off >>= 1) m = fmaxf(m, __shfl_xor_sync(0xffffffffu, m, off));
        float e = (lane < K) ? expf(val - m) : 0.f;
        float s = e;
        #pragma unroll
        for (int off = 16; off; off >>= 1) s += __shfl_xor_sync(0xffffffffu, s, off);
        s_attn[lane] = e / s;
    }
    __syncthreads();

    float4 acc = make_float4(0.f, 0.f, 0.f, 0.f);
    #pragma unroll
    for (int j = 0; j < 7; ++j) {
        int k = warp + 4 * j;
        if (k < K) {
            float a = s_attn[k];
            acc.x += a * v[j].x; acc.y += a * v[j].y;
            acc.z += a * v[j].z; acc.w += a * v[j].w;
        }
    }
    s_part[warp][lane] = acc;
    __syncthreads();

    if (warp == 0) {
        float4 r0 = s_part[0][lane], r1 = s_part[1][lane];
        float4 r2 = s_part[2][lane], r3 = s_part[3][lane];
        float ce = 1.f + epsp[0];
        float4 sf = sv[lane];
        float4 r;
        r.x = r0.x + r1.x + r2.x + r3.x + ce * sf.x;
        r.y = r0.y + r1.y + r2.y + r3.y + ce * sf.y;
        r.z = r0.z + r1.z + r2.z + r3.z + ce * sf.z;
        r.w = r0.w + r1.w + r2.w + r3.w + ce * sf.w;
        ((float4*)g_z)[(size_t)n * 32 + lane] = r;
    }
}

// ---------------- fp16 m16n8k16 GEMM: BM=128 as two 64-row halves reusing B, one wave ----------
// smem: [0:1024) scale|shift, As half[64][136], Bs half[128][136]
#define ASTRIDE 136
#define SMEM_BYTES (1024 + 64 * ASTRIDE * 2 + 128 * ASTRIDE * 2)

template <bool IN_BN>
__global__ __launch_bounds__(256, 3) void gemm_mma(
    const float* __restrict__ A, const __half* __restrict__ Bth,
    const float* __restrict__ sumIn, const float* __restrict__ sqsIn,
    const float* __restrict__ gIn, const float* __restrict__ beIn,
    float* __restrict__ Y, float* __restrict__ sumOut, float* __restrict__ sqsOut,
    float invN, int N)
{
    extern __shared__ char smc[];
    float* s_scale = (float*)smc;                     // 128
    float* s_shift = (float*)smc + 128;               // 128
    __half* As = (__half*)(smc + 1024);               // 64*136
    __half* Bs = As + 64 * ASTRIDE;                   // 128*136

    const int tid = threadIdx.x;
    const int wid = tid >> 5, lane = tid & 31;
    const int g = lane >> 2, t = lane & 3;
    const int warprow = wid & 1;
    const int warpcol = wid >> 1;

    // inline BN finalize
    if (IN_BN && tid < 128) {
        float m = sumIn[tid] * invN;
        float var = sqsIn[tid] * invN - m * m;
        float s = gIn[tid] * rsqrtf(var + BN_EPS);
        s_scale[tid] = s;
        s_shift[tid] = beIn[tid] - m * s;
    }

    // B: copy fp16 weights once (4096 uint2), reused by both halves
    {
        const uint2* Bi = (const uint2*)Bth;
        #pragma unroll
        for (int i = 0; i < 16; ++i) {
            int idx = tid + i * 256;
            int n = idx >> 5, q = idx & 31;
            *(uint2*)(Bs + n * ASTRIDE + q * 4) = Bi[idx];
        }
    }
    if (IN_BN) __syncthreads();   // scale/shift ready (also orders nothing harmful when !IN_BN)

    // stats accumulators persist across both halves
    float cs[8], cq[8];
    #pragma unroll
    for (int j = 0; j < 8; ++j) { cs[j] = 0.f; cq[j] = 0.f; }

    #pragma unroll
    for (int h = 0; h < 2; ++h) {
        const int rowBase = blockIdx.x * 128 + h * 64;

        if (h > 0) __syncthreads();   // all warps done reading As from previous half

        // A: 64 rows x 128, BN+lrelu fused, fp16-converted; rows >= N exact zero
        {
            const float4* Ag4 = (const float4*)A;
            #pragma unroll
            for (int i = 0; i < 8; ++i) {
                int idx = tid + i * 256;
                int row = idx >> 5, q = idx & 31;
                int grow = rowBase + row;
                float4 a = make_float4(0.f, 0.f, 0.f, 0.f);
                if (grow < N) {
                    a = Ag4[(size_t)grow * 32 + q];
                    if (IN_BN) {
                        float4 sc = *(const float4*)&s_scale[q * 4];
                        float4 sh = *(const float4*)&s_shift[q * 4];
                        a.x = lrelu(sc.x * a.x + sh.x);
                        a.y = lrelu(sc.y * a.y + sh.y);
                        a.z = lrelu(sc.z * a.z + sh.z);
                        a.w = lrelu(sc.w * a.w + sh.w);
                    }
                }
                __half2 h01 = __floats2half2_rn(a.x, a.y);
                __half2 h23 = __floats2half2_rn(a.z, a.w);
                uint2 pk;
                pk.x = *(uint32_t*)&h01;
                pk.y = *(uint32_t*)&h23;
                *(uint2*)(As + row * ASTRIDE + q * 4) = pk;
            }
        }
        __syncthreads();

        float acc[2][4][4];
        #pragma unroll
        for (int m = 0; m < 2; ++m)
            #pragma unroll
            for (int n = 0; n < 4; ++n)
                #pragma unroll
                for (int j = 0; j < 4; ++j) acc[m][n][j] = 0.f;

        #pragma unroll
        for (int ks = 0; ks < 8; ++ks) {
            const int k0 = ks * 16;
            uint32_t af[2][4];
            #pragma unroll
            for (int m = 0; m < 2; ++m) {
                const __half* p = As + (warprow * 32 + m * 16 + g) * ASTRIDE + k0 + 2 * t;
                af[m][0] = *(const uint32_t*)p;
                af[m][1] = *(const uint32_t*)(p + 8 * ASTRIDE);
                af[m][2] = *(const uint32_t*)(p + 8);
                af[m][3] = *(const uint32_t*)(p + 8 * ASTRIDE + 8);
            }
            #pragma unroll
            for (int n = 0; n < 4; ++n) {
                const __half* pb = Bs + (warpcol * 32 + n * 8 + g) * ASTRIDE + k0 + 2 * t;
                uint32_t b0 = *(const uint32_t*)pb;
                uint32_t b1 = *(const uint32_t*)(pb + 8);
                #pragma unroll
                for (int m = 0; m < 2; ++m) {
                    asm volatile(
                        "mma.sync.aligned.m16n8k16.row.col.f32.f16.f16.f32 "
                        "{%0,%1,%2,%3}, {%4,%5,%6,%7}, {%8,%9}, {%0,%1,%2,%3};"
                        : "+f"(acc[m][n][0]), "+f"(acc[m][n][1]),
                          "+f"(acc[m][n][2]), "+f"(acc[m][n][3])
                        : "r"(af[m][0]), "r"(af[m][1]), "r"(af[m][2]), "r"(af[m][3]),
                          "r"(b0), "r"(b1));
                }
            }
        }
        __syncthreads();   // all warps done with As before next half overwrites / red reuse

        // store + accumulate per-column stats (rows >= N contribute exact zeros)
        #pragma unroll
        for (int m = 0; m < 2; ++m) {
            int r = rowBase + warprow * 32 + m * 16 + g;
            #pragma unroll
            for (int n = 0; n < 4; ++n) {
                int c = warpcol * 32 + n * 8 + 2 * t;
                float y0 = acc[m][n][0], y1 = acc[m][n][1];
                float y2 = acc[m][n][2], y3 = acc[m][n][3];
                *(float2*)&Y[(size_t)r * 128 + c]       = make_float2(y0, y1);
                *(float2*)&Y[(size_t)(r + 8) * 128 + c] = make_float2(y2, y3);
                int j = n * 2;
                cs[j]     += y0 + y2;  cq[j]     += y0 * y0 + y2 * y2;
                cs[j + 1] += y1 + y3;  cq[j + 1] += y1 * y1 + y3 * y3;
            }
        }
    }

    // stats reduce once per CTA
    #pragma unroll
    for (int off = 4; off < 32; off <<= 1) {
        #pragma unroll
        for (int j = 0; j < 8; ++j) {
            cs[j] += __shfl_xor_sync(0xffffffffu, cs[j], off);
            cq[j] += __shfl_xor_sync(0xffffffffu, cq[j], off);
        }
    }

    // reduce scratch lives in dead As area (scale/shift must stay intact is moot now, but safe)
    float* red_s = (float*)As;             // 8 warps x 32 cols
    float* red_q = (float*)As + 256;
    if (lane < 4) {
        #pragma unroll
        for (int j = 0; j < 8; ++j) {
            int n = j >> 1;
            int cl = n * 8 + 2 * lane + (j & 1);
            red_s[wid * 32 + cl] = cs[j];
            red_q[wid * 32 + cl] = cq[j];
        }
    }
    __syncthreads();
    if (tid < 128) {
        int wc = tid >> 5, cl = tid & 31;
        float ssum = red_s[(2 * wc) * 32 + cl] + red_s[(2 * wc + 1) * 32 + cl];
        float qsum = red_q[(2 * wc) * 32 + cl] + red_q[(2 * wc + 1) * 32 + cl];
        atomicAdd(&sumOut[wc * 32 + cl], ssum);
        atomicAdd(&sqsOut[wc * 32 + cl], qsum);
    }
}

// ---------------- final BN + leaky_relu apply (inline BN finalize) ----------------
__global__ __launch_bounds__(256) void apply_kernel(
    const float* __restrict__ Y,
    const float* __restrict__ sumIn, const float* __restrict__ sqsIn,
    const float* __restrict__ gIn, const float* __restrict__ beIn,
    float* __restrict__ out, float invN, int N)
{
    __shared__ float s_scale[128], s_shift[128];
    int tid = threadIdx.x;
    if (tid < 128) {
        float m = sumIn[tid] * invN;
        float var = sqsIn[tid] * invN - m * m;
        float s = gIn[tid] * rsqrtf(var + BN_EPS);
        s_scale[tid] = s;
        s_shift[tid] = beIn[tid] - m * s;
    }
    __syncthreads();

    size_t i = (size_t)blockIdx.x * blockDim.x + tid;
    if (i < (size_t)N * 32) {
        int c = (int)(i & 31);
        float4 sc = *(const float4*)&s_scale[c * 4];
        float4 sh = *(const float4*)&s_shift[c * 4];
        float4 y = ((const float4*)Y)[i];
        float4 o;
        o.x = lrelu(sc.x * y.x + sh.x);
        o.y = lrelu(sc.y * y.y + sh.y);
        o.z = lrelu(sc.z * y.z + sh.z);
        o.w = lrelu(sc.w * y.w + sh.w);
        ((float4*)out)[i] = o;
    }
}

// ---------------- launch ----------------
extern "C" void kernel_launch(void* const* d_in, const int* in_sizes, int n_in,
                              void* d_out, int out_size) {
    const float* self  = (const float*)d_in[0];
    const float* neigh = (const float*)d_in[1];
    const float* W_t   = (const float*)d_in[2];
    const float* a_att = (const float*)d_in[3];
    const float* epsp  = (const float*)d_in[4];
    const float* W1 = (const float*)d_in[5];
    const float* g1 = (const float*)d_in[7];
    const float* be1 = (const float*)d_in[8];
    const float* W2 = (const float*)d_in[9];
    const float* g2 = (const float*)d_in[11];
    const float* be2 = (const float*)d_in[12];
    const float* W3 = (const float*)d_in[13];
    const float* g3 = (const float*)d_in[15];
    const float* be3 = (const float*)d_in[16];

    int N = in_sizes[0] / 128;
    int K = (int)((long long)in_sizes[1] / ((long long)N * 128));

    float *z, *bufA, *bufB, *sum, *sqs;
    __half* Bth;
    cudaGetSymbolAddress((void**)&z,    g_z);
    cudaGetSymbolAddress((void**)&bufA, g_bufA);
    cudaGetSymbolAddress((void**)&bufB, g_bufB);
    cudaGetSymbolAddress((void**)&Bth,  g_Bth);
    cudaGetSymbolAddress((void**)&sum,  g_sum);
    cudaGetSymbolAddress((void**)&sqs,  g_sqs);

    cudaFuncSetAttribute(gemm_mma<false>, cudaFuncAttributeMaxDynamicSharedMemorySize, SMEM_BYTES);
    cudaFuncSetAttribute(gemm_mma<true>,  cudaFuncAttributeMaxDynamicSharedMemorySize, SMEM_BYTES);

    float invN = 1.f / (float)N;
    int gemmGrid = (N + 127) / 128;    // 391 CTAs -> one wave at 3 CTAs/SM

    prep_all_kernel<<<193, 256>>>(W_t, a_att, W1, W2, W3);

    attn_kernel<<<N, 128>>>(self, neigh, epsp, N, K);

    // y1 = z @ Wc (bias no-op under BN), fused stats -> sum[0]
    gemm_mma<false><<<gemmGrid, 256, SMEM_BYTES>>>(
        z, Bth, nullptr, nullptr, nullptr, nullptr, bufA, sum, sqs, invN, N);

    // y2 = act1(y1) @ W2, inline bn_fin(layer0), fused stats -> sum[1]
    gemm_mma<true><<<gemmGrid, 256, SMEM_BYTES>>>(
        bufA, Bth + 16384, sum, sqs, g1, be1, bufB, sum + 128, sqs + 128, invN, N);

    // y3 = act2(y2) @ W3, inline bn_fin(layer1), fused stats -> sum[2]
    gemm_mma<true><<<gemmGrid, 256, SMEM_BYTES>>>(
        bufB, Bth + 32768, sum + 128, sqs + 128, g2, be2, bufA, sum + 256, sqs + 256, invN, N);

    // out = act3(y3), inline bn_fin(layer2)
    int applyGrid = (int)(((size_t)N * 32 + 255) / 256);
    apply_kernel<<<applyGrid, 256>>>(bufA, sum + 256, sqs + 256, g3, be3, (float*)d_out, invN, N);
}